// round 3
// baseline (speedup 1.0000x reference)
#include <cuda_runtime.h>
#include <math.h>

#define B_   128
#define T_   256
#define H_   512
#define G4_  2048   // 4*H

// ---------------- scratch (device globals; no allocation allowed) -------------
// P: input projections, layout [dir][t*B + b][4H]  (per-dir stride 32768*2048)
__device__ float    g_P[134217728];     // 2 * 32768 * 2048  (536 MB)
// inter: layer-0 output, layout [dir][t*B + b][H]
__device__ float    g_inter[33554432];  // 2 * 32768 * 512   (134 MB)
// h ping-pong: [pingpong][dir][B*H]
__device__ float    g_h[262144];        // 2 * 2 * 65536
__device__ unsigned g_arrive[2];
__device__ unsigned g_gen[2];

// ---------------- helpers ----------------------------------------------------
__device__ __forceinline__ float f2tf(float x) {
    unsigned u;
    asm("cvt.rna.tf32.f32 %0, %1;" : "=r"(u) : "f"(x));
    return __uint_as_float(u);
}

__device__ __forceinline__ void mma8(float* c, const unsigned* a, const unsigned* b) {
    asm volatile(
        "mma.sync.aligned.m16n8k8.row.col.f32.tf32.tf32.f32 "
        "{%0,%1,%2,%3}, {%4,%5,%6,%7}, {%8,%9}, {%0,%1,%2,%3};\n"
        : "+f"(c[0]), "+f"(c[1]), "+f"(c[2]), "+f"(c[3])
        : "r"(a[0]), "r"(a[1]), "r"(a[2]), "r"(a[3]), "r"(b[0]), "r"(b[1]));
}

__device__ __forceinline__ float sigm(float x) { return 1.f / (1.f + expf(-x)); }

// ---------------- reset (h0 = 0, barrier counters = 0) -----------------------
__global__ void reset_kernel() {
    int i = blockIdx.x * blockDim.x + threadIdx.x;
    if (i < 131072) g_h[i] = 0.f;             // pingpong buffer 0, both dirs
    if (i < 2) { g_arrive[i] = 0u; g_gen[i] = 0u; }
}

// ---------------- input projection: P = A @ Wx + b ---------------------------
// grid (32, 256, 2): x = N-tile (64 cols), y = t, z = dir.  BM=128 (all of B).
// amode 0: A = x, row (b) at x[(b*T + t)*H]
// amode 1: A = g_inter[dir], row at inter[(t*B + b)*H]
__global__ void __launch_bounds__(256) xproj_kernel(
    const float* __restrict__ x, const float* __restrict__ Wx,
    const float* __restrict__ bias, int layer, int amode)
{
    __shared__ float As[128][36];   // BK=32, pad 36
    __shared__ float Bs[32][72];    // BN=64, pad 72

    const int tid  = threadIdx.x;
    const int dir  = blockIdx.z;
    const int t    = blockIdx.y;
    const int col0 = blockIdx.x * 64;
    const float* W  = Wx   + (size_t)(layer * 2 + dir) * H_ * G4_;
    const float* bs = bias + (layer * 2 + dir) * G4_;
    const float* Ab = amode ? (g_inter + (size_t)dir * 16777216) : x;
    const int lane = tid & 31, warp = tid >> 5;
    const int wm = warp >> 1, wn = warp & 1;   // 4x2 warp grid, warp tile 32x32

    float acc[2][4][4];
    #pragma unroll
    for (int i = 0; i < 2; i++)
        #pragma unroll
        for (int j = 0; j < 4; j++)
            #pragma unroll
            for (int k = 0; k < 4; k++) acc[i][j][k] = 0.f;

    for (int kc = 0; kc < 16; kc++) {
        // A tile 128x32
        #pragma unroll
        for (int i = 0; i < 4; i++) {
            int lin = tid + i * 256;
            int r = lin >> 3, c4 = (lin & 7) << 2;
            const float* src = Ab +
                (amode ? ((size_t)(t * 128 + r)) * 512
                       : ((size_t)(r * 256 + t)) * 512) + kc * 32 + c4;
            float4 v = *reinterpret_cast<const float4*>(src);
            *reinterpret_cast<float4*>(&As[r][c4]) =
                make_float4(f2tf(v.x), f2tf(v.y), f2tf(v.z), f2tf(v.w));
        }
        // B tile 32x64
        #pragma unroll
        for (int i = 0; i < 2; i++) {
            int lin = tid + i * 256;
            int r = lin >> 4, c4 = (lin & 15) << 2;
            const float* src = W + (size_t)(kc * 32 + r) * G4_ + col0 + c4;
            float4 v = *reinterpret_cast<const float4*>(src);
            *reinterpret_cast<float4*>(&Bs[r][c4]) =
                make_float4(f2tf(v.x), f2tf(v.y), f2tf(v.z), f2tf(v.w));
        }
        __syncthreads();
        #pragma unroll
        for (int s = 0; s < 4; s++) {
            int ka = s * 8 + (lane & 3);
            unsigned a[2][4];
            #pragma unroll
            for (int mt = 0; mt < 2; mt++) {
                int r = wm * 32 + mt * 16 + (lane >> 2);
                a[mt][0] = __float_as_uint(As[r][ka]);
                a[mt][1] = __float_as_uint(As[r + 8][ka]);
                a[mt][2] = __float_as_uint(As[r][ka + 4]);
                a[mt][3] = __float_as_uint(As[r + 8][ka + 4]);
            }
            unsigned bf[4][2];
            #pragma unroll
            for (int nt = 0; nt < 4; nt++) {
                int c = wn * 32 + nt * 8 + (lane >> 2);
                bf[nt][0] = __float_as_uint(Bs[s * 8 + (lane & 3)][c]);
                bf[nt][1] = __float_as_uint(Bs[s * 8 + 4 + (lane & 3)][c]);
            }
            #pragma unroll
            for (int mt = 0; mt < 2; mt++)
                #pragma unroll
                for (int nt = 0; nt < 4; nt++)
                    mma8(acc[mt][nt], a[mt], bf[nt]);
        }
        __syncthreads();
    }

    // epilogue: + bias, write P[dir][t*128 + b][col]
    float* Pd = g_P + (size_t)dir * 67108864 + (size_t)t * 128 * 2048;
    #pragma unroll
    for (int nt = 0; nt < 4; nt++) {
        int cg = col0 + wn * 32 + nt * 8 + 2 * (lane & 3);
        float b0 = bs[cg], b1 = bs[cg + 1];
        #pragma unroll
        for (int mt = 0; mt < 2; mt++) {
            int r = wm * 32 + mt * 16 + (lane >> 2);
            *reinterpret_cast<float2*>(Pd + (size_t)r * 2048 + cg) =
                make_float2(acc[mt][nt][0] + b0, acc[mt][nt][1] + b1);
            *reinterpret_cast<float2*>(Pd + (size_t)(r + 8) * 2048 + cg) =
                make_float2(acc[mt][nt][2] + b0, acc[mt][nt][3] + b1);
        }
    }
}

// ---------------- persistent recurrent scan ----------------------------------
// grid (64, 2): 64 blocks per direction, block owns 8 hidden units (all 4 gates),
// all 128 batch rows. c-state lives in registers. One grid barrier per step.
#define SCAN_SMEM ((512 * 36 + 2 * 128 * 36) * 4)   // 110592 B

__global__ void __launch_bounds__(256, 1) scan_kernel(
    const float* __restrict__ Wh_all, int layer, int last, float* __restrict__ out)
{
    extern __shared__ float sm[];
    float* Whs = sm;                 // [512][36]  tf32 Wh panel (resident)
    float* Hs  = sm + 512 * 36;      // [2][128][36] h chunk double-buffer

    const int tid  = threadIdx.x;
    const int lane = tid & 31, warp = tid >> 5;
    const int dir  = blockIdx.y;
    const int j0   = blockIdx.x * 8;  // hidden-unit base
    const float* Wh = Wh_all + (size_t)(layer * 2 + dir) * H_ * G4_;

    // preload Wh panel: rows k=0..511, cols {g*512 + j0 .. +7} for g=0..3
    #pragma unroll 4
    for (int i = 0; i < 16; i++) {
        int lin = tid + i * 256;               // float4 index 0..4095
        int r = lin >> 3, q = lin & 7;
        int g = q >> 1, hf = q & 1;
        const float* src = Wh + (size_t)r * 2048 + g * 512 + j0 + hf * 4;
        float4 v = *reinterpret_cast<const float4*>(src);
        *reinterpret_cast<float4*>(Whs + r * 36 + g * 8 + hf * 4) =
            make_float4(f2tf(v.x), f2tf(v.y), f2tf(v.z), f2tf(v.w));
    }
    __syncthreads();

    const int row_base = warp * 16 + (lane >> 2);
    const int ucol     = j0 + 2 * (lane & 3);
    float creg[4] = {0.f, 0.f, 0.f, 0.f};
    int p = 0;

    for (int s = 0; s < 256; s++) {
        const int t = (dir == 0) ? s : (255 - s);

        // prefetch P for this step's epilogue (latency hidden by k-loop)
        const float* Pp = g_P + (size_t)dir * 67108864 + (size_t)t * 128 * 2048;
        float pv[4][4];
        #pragma unroll
        for (int g = 0; g < 4; g++)
            #pragma unroll
            for (int k = 0; k < 4; k++) {
                int r = row_base + ((k >> 1) << 3);
                pv[g][k] = Pp[(size_t)r * 2048 + g * 512 + ucol + (k & 1)];
            }

        const float* hr = g_h + ((p * 2 + dir) << 16);
        float acc[4][4];
        #pragma unroll
        for (int g = 0; g < 4; g++)
            #pragma unroll
            for (int k = 0; k < 4; k++) acc[g][k] = 0.f;

        // preload h chunk 0
        #pragma unroll
        for (int i = 0; i < 4; i++) {
            int lin = tid + i * 256;
            int r = lin >> 3, c4 = (lin & 7) << 2;
            float4 v = *reinterpret_cast<const float4*>(hr + r * 512 + c4);
            *reinterpret_cast<float4*>(Hs + r * 36 + c4) =
                make_float4(f2tf(v.x), f2tf(v.y), f2tf(v.z), f2tf(v.w));
        }

        for (int kc = 0; kc < 16; kc++) {
            __syncthreads();
            if (kc < 15) {
                float* Hb = Hs + ((kc + 1) & 1) * (128 * 36);
                #pragma unroll
                for (int i = 0; i < 4; i++) {
                    int lin = tid + i * 256;
                    int r = lin >> 3, c4 = (lin & 7) << 2;
                    float4 v = *reinterpret_cast<const float4*>(
                        hr + r * 512 + (kc + 1) * 32 + c4);
                    *reinterpret_cast<float4*>(Hb + r * 36 + c4) =
                        make_float4(f2tf(v.x), f2tf(v.y), f2tf(v.z), f2tf(v.w));
                }
            }
            const float* Hb = Hs + (kc & 1) * (128 * 36);
            #pragma unroll
            for (int s4 = 0; s4 < 4; s4++) {
                int kk = s4 * 8;
                unsigned a[4];
                a[0] = __float_as_uint(Hb[row_base * 36 + kk + (lane & 3)]);
                a[1] = __float_as_uint(Hb[(row_base + 8) * 36 + kk + (lane & 3)]);
                a[2] = __float_as_uint(Hb[row_base * 36 + kk + 4 + (lane & 3)]);
                a[3] = __float_as_uint(Hb[(row_base + 8) * 36 + kk + 4 + (lane & 3)]);
                #pragma unroll
                for (int g = 0; g < 4; g++) {
                    unsigned bb[2];
                    int br = kc * 32 + kk + (lane & 3);
                    bb[0] = __float_as_uint(Whs[br * 36 + g * 8 + (lane >> 2)]);
                    bb[1] = __float_as_uint(Whs[(br + 4) * 36 + g * 8 + (lane >> 2)]);
                    mma8(acc[g], a, bb);
                }
            }
        }

        // LSTM pointwise epilogue — all 4 gates for (b, j) live on this thread
        float* hw = g_h + (((1 - p) * 2 + dir) << 16);
        #pragma unroll
        for (int k = 0; k < 4; k++) {
            float i_ = sigm(acc[0][k] + pv[0][k]);
            float f_ = sigm(acc[1][k] + pv[1][k]);
            float gg = tanhf(acc[2][k] + pv[2][k]);
            float o_ = sigm(acc[3][k] + pv[3][k]);
            float cn = f_ * creg[k] + i_ * gg;
            creg[k] = cn;
            float hn = o_ * tanhf(cn);
            int r = row_base + ((k >> 1) << 3);
            int u = ucol + (k & 1);
            hw[r * 512 + u] = hn;
            if (!last)
                g_inter[(size_t)dir * 16777216 + ((size_t)t * 128 + r) * 512 + u] = hn;
            else
                out[((size_t)r * 256 + t) * 1024 + dir * 512 + u] = hn;
        }

        // per-direction grid barrier (all 64 blocks of this dir are co-resident:
        // 128 blocks total < 148 SMs -> single wave, no deadlock possible)
        __syncthreads();
        if (tid == 0) {
            __threadfence();
            unsigned a = atomicAdd(&g_arrive[dir], 1u);
            if (a == 63u) {
                atomicExch(&g_arrive[dir], 0u);
                __threadfence();
                atomicExch(&g_gen[dir], (unsigned)(s + 1));
            } else {
                while (atomicAdd(&g_gen[dir], 0u) < (unsigned)(s + 1)) {
                    __nanosleep(64);
                }
            }
            __threadfence();
        }
        __syncthreads();
        p ^= 1;
    }
}

// ---------------- launch ------------------------------------------------------
extern "C" void kernel_launch(void* const* d_in, const int* in_sizes, int n_in,
                              void* d_out, int out_size)
{
    (void)in_sizes; (void)n_in; (void)out_size;
    const float* x  = (const float*)d_in[0];
    const float* Wx = (const float*)d_in[1];
    const float* Wh = (const float*)d_in[2];
    const float* b  = (const float*)d_in[3];
    float* out = (float*)d_out;

    static int smem_set = 0;
    if (!smem_set) {
        cudaFuncSetAttribute(scan_kernel,
                             cudaFuncAttributeMaxDynamicSharedMemorySize, SCAN_SMEM);
        smem_set = 1;
    }

    dim3 gx(32, 256, 2);
    dim3 gs(64, 2);

    // layer 0
    reset_kernel<<<512, 256>>>();
    xproj_kernel<<<gx, 256>>>(x, Wx, b, 0, 0);
    scan_kernel<<<gs, 256, SCAN_SMEM>>>(Wh, 0, 0, out);
    // layer 1
    reset_kernel<<<512, 256>>>();
    xproj_kernel<<<gx, 256>>>(x, Wx, b, 1, 1);
    scan_kernel<<<gs, 256, SCAN_SMEM>>>(Wh, 1, 1, out);
}

// round 5
// speedup vs baseline: 1.8147x; 1.8147x over previous
#include <cuda_runtime.h>
#include <math.h>

#define B_   128
#define T_   256
#define H_   512
#define G4_  2048   // 4*H

// ---------------- scratch (device globals; no allocation allowed) -------------
// P: input projections, layout [dir][t*B + b][4H]
__device__ float    g_P[134217728];     // 2 * 32768 * 2048
// inter: layer-0 output, layout [dir][t*B + b][H]
__device__ float    g_inter[33554432];  // 2 * 32768 * 512
// h in mma-A-fragment order: [pp][dir][slice(64)][rowtile(8)][lane(32)] float4
__device__ float4   g_hf[65536];        // 2*2*64*8*32 float4 = 4 MB
__device__ unsigned g_arrive[2];        // cumulative, zero-init
__device__ unsigned g_gen[2];           // cumulative, zero-init

// ---------------- helpers ----------------------------------------------------
__device__ __forceinline__ float f2tf(float x) {
    unsigned u;
    asm("cvt.rna.tf32.f32 %0, %1;" : "=r"(u) : "f"(x));
    return __uint_as_float(u);
}

__device__ __forceinline__ void mma8(float* c, const unsigned* a, const unsigned* b) {
    asm volatile(
        "mma.sync.aligned.m16n8k8.row.col.f32.tf32.tf32.f32 "
        "{%0,%1,%2,%3}, {%4,%5,%6,%7}, {%8,%9}, {%0,%1,%2,%3};\n"
        : "+f"(c[0]), "+f"(c[1]), "+f"(c[2]), "+f"(c[3])
        : "r"(a[0]), "r"(a[1]), "r"(a[2]), "r"(a[3]), "r"(b[0]), "r"(b[1]));
}

__device__ __forceinline__ float sigm(float x) { return 1.f / (1.f + expf(-x)); }

// ---------------- input projection: P = A @ Wx + b ---------------------------
// grid (32, 256, 2): x = N-tile (64 cols), y = t, z = dir.  BM=128 (all of B).
__global__ void __launch_bounds__(256) xproj_kernel(
    const float* __restrict__ x, const float* __restrict__ Wx,
    const float* __restrict__ bias, int layer, int amode)
{
    __shared__ float As[128][36];
    __shared__ float Bs[32][72];

    const int tid  = threadIdx.x;
    const int dir  = blockIdx.z;
    const int t    = blockIdx.y;
    const int col0 = blockIdx.x * 64;
    const float* W  = Wx   + (size_t)(layer * 2 + dir) * H_ * G4_;
    const float* bs = bias + (layer * 2 + dir) * G4_;
    const float* Ab = amode ? (g_inter + (size_t)dir * 16777216) : x;
    const int lane = tid & 31, warp = tid >> 5;
    const int wm = warp >> 1, wn = warp & 1;

    float acc[2][4][4];
    #pragma unroll
    for (int i = 0; i < 2; i++)
        #pragma unroll
        for (int j = 0; j < 4; j++)
            #pragma unroll
            for (int k = 0; k < 4; k++) acc[i][j][k] = 0.f;

    for (int kc = 0; kc < 16; kc++) {
        #pragma unroll
        for (int i = 0; i < 4; i++) {
            int lin = tid + i * 256;
            int r = lin >> 3, c4 = (lin & 7) << 2;
            const float* src = Ab +
                (amode ? ((size_t)(t * 128 + r)) * 512
                       : ((size_t)(r * 256 + t)) * 512) + kc * 32 + c4;
            float4 v = *reinterpret_cast<const float4*>(src);
            *reinterpret_cast<float4*>(&As[r][c4]) =
                make_float4(f2tf(v.x), f2tf(v.y), f2tf(v.z), f2tf(v.w));
        }
        #pragma unroll
        for (int i = 0; i < 2; i++) {
            int lin = tid + i * 256;
            int r = lin >> 4, c4 = (lin & 15) << 2;
            const float* src = W + (size_t)(kc * 32 + r) * G4_ + col0 + c4;
            float4 v = *reinterpret_cast<const float4*>(src);
            *reinterpret_cast<float4*>(&Bs[r][c4]) =
                make_float4(f2tf(v.x), f2tf(v.y), f2tf(v.z), f2tf(v.w));
        }
        __syncthreads();
        #pragma unroll
        for (int s = 0; s < 4; s++) {
            int ka = s * 8 + (lane & 3);
            unsigned a[2][4];
            #pragma unroll
            for (int mt = 0; mt < 2; mt++) {
                int r = wm * 32 + mt * 16 + (lane >> 2);
                a[mt][0] = __float_as_uint(As[r][ka]);
                a[mt][1] = __float_as_uint(As[r + 8][ka]);
                a[mt][2] = __float_as_uint(As[r][ka + 4]);
                a[mt][3] = __float_as_uint(As[r + 8][ka + 4]);
            }
            unsigned bf[4][2];
            #pragma unroll
            for (int nt = 0; nt < 4; nt++) {
                int c = wn * 32 + nt * 8 + (lane >> 2);
                bf[nt][0] = __float_as_uint(Bs[s * 8 + (lane & 3)][c]);
                bf[nt][1] = __float_as_uint(Bs[s * 8 + 4 + (lane & 3)][c]);
            }
            #pragma unroll
            for (int mt = 0; mt < 2; mt++)
                #pragma unroll
                for (int nt = 0; nt < 4; nt++)
                    mma8(acc[mt][nt], a[mt], bf[nt]);
        }
        __syncthreads();
    }

    float* Pd = g_P + (size_t)dir * 67108864 + (size_t)t * 128 * 2048;
    #pragma unroll
    for (int nt = 0; nt < 4; nt++) {
        int cg = col0 + wn * 32 + nt * 8 + 2 * (lane & 3);
        float b0 = bs[cg], b1 = bs[cg + 1];
        #pragma unroll
        for (int mt = 0; mt < 2; mt++) {
            int r = wm * 32 + mt * 16 + (lane >> 2);
            *reinterpret_cast<float2*>(Pd + (size_t)r * 2048 + cg) =
                make_float2(acc[mt][nt][0] + b0, acc[mt][nt][1] + b1);
            *reinterpret_cast<float2*>(Pd + (size_t)(r + 8) * 2048 + cg) =
                make_float2(acc[mt][nt][2] + b0, acc[mt][nt][3] + b1);
        }
    }
}

// ---------------- persistent recurrent scan ----------------------------------
// grid (64, 2): 64 blocks/dir, block owns 8 hidden units (= one k8 mma slice),
// warp owns 16 batch rows (= one m16 row-tile). h lives in gmem in mma-A
// fragment order; Wh B-fragments prepacked in smem. c stays in registers.
// smem: Whb[64 slices][4 gates][32 lanes] float2  (16384 floats, 64 KB)
//       Ht[8 warps][16][9] repack tiles           (1152 floats)
#define SCAN_SMEM ((16384 + 8 * 144) * 4)

__global__ void __launch_bounds__(256, 1) scan_kernel(
    const float* __restrict__ Wh_all, int layer, int last, float* __restrict__ out)
{
    extern __shared__ float sm[];
    float2* Whb = reinterpret_cast<float2*>(sm);   // [ (s*4+g)*32 + lane ]
    float*  Ht  = sm + 16384;                      // per-warp [16][9]

    const int tid  = threadIdx.x;
    const int lane = tid & 31, warp = tid >> 5;
    const int dir  = blockIdx.y;
    const int j0   = blockIdx.x * 8;               // hidden-unit base = slice*8
    const int myslice = blockIdx.x;
    const float* Wh = Wh_all + (size_t)(layer * 2 + dir) * H_ * G4_;

    __shared__ unsigned s_genbase;
    if (tid == 0) s_genbase = atomicAdd(&g_gen[dir], 0u);

    // prepack Wh B-fragments: Whb[(s*4+g)*32+lane] = {Wh[k,n], Wh[k+4,n]},
    // k = s*8 + (lane&3), n = g*512 + j0 + (lane>>2)
    for (int idx = tid; idx < 8192; idx += 256) {
        int s = idx >> 7, r = idx & 127;
        int g = r >> 5, l = r & 31;
        int k = s * 8 + (l & 3);
        int n = g * 512 + j0 + (l >> 2);
        Whb[idx] = make_float2(f2tf(Wh[(size_t)k * 2048 + n]),
                               f2tf(Wh[(size_t)(k + 4) * 2048 + n]));
    }
    __syncthreads();
    const unsigned gen_base = s_genbase;

    const int row_base = warp * 16 + (lane >> 2);
    const int ucol     = j0 + 2 * (lane & 3);
    float* ht = Ht + warp * 144;
    float creg[4] = {0.f, 0.f, 0.f, 0.f};
    int p = 0;

    #pragma unroll 1
    for (int s = 0; s < 256; s++) {
        const int t = (dir == 0) ? s : (255 - s);

        // prefetch P (epilogue addend) early
        const float* Pp = g_P + (size_t)dir * 67108864 + (size_t)t * 128 * 2048;
        float pv[4][4];
        #pragma unroll
        for (int g = 0; g < 4; g++) {
            float2 v0 = *reinterpret_cast<const float2*>(
                Pp + (size_t)row_base * 2048 + g * 512 + ucol);
            float2 v1 = *reinterpret_cast<const float2*>(
                Pp + (size_t)(row_base + 8) * 2048 + g * 512 + ucol);
            pv[g][0] = v0.x; pv[g][1] = v0.y; pv[g][2] = v1.x; pv[g][3] = v1.y;
        }

        float acc[4][4];
        #pragma unroll
        for (int g = 0; g < 4; g++)
            #pragma unroll
            for (int k = 0; k < 4; k++) acc[g][k] = 0.f;

        if (s > 0) {
            // h @ Wh: 64 k-slices, A-frags straight from gmem (fragment layout)
            const float4* hp = g_hf + ((p * 2 + dir) << 14) + warp * 32 + lane;
            float4 buf[2][4];
            #pragma unroll
            for (int j = 0; j < 4; j++) buf[0][j] = hp[j * 256];
            #pragma unroll 2
            for (int sb = 0; sb < 16; sb++) {
                if (sb < 15) {
                    #pragma unroll
                    for (int j = 0; j < 4; j++)
                        buf[(sb + 1) & 1][j] = hp[((sb + 1) * 4 + j) * 256];
                }
                #pragma unroll
                for (int j = 0; j < 4; j++) {
                    int s4 = sb * 4 + j;
                    unsigned a[4];
                    a[0] = __float_as_uint(buf[sb & 1][j].x);
                    a[1] = __float_as_uint(buf[sb & 1][j].y);
                    a[2] = __float_as_uint(buf[sb & 1][j].z);
                    a[3] = __float_as_uint(buf[sb & 1][j].w);
                    #pragma unroll
                    for (int g = 0; g < 4; g++) {
                        float2 bv = Whb[(s4 * 4 + g) * 32 + lane];
                        unsigned bb[2];
                        bb[0] = __float_as_uint(bv.x);
                        bb[1] = __float_as_uint(bv.y);
                        mma8(acc[g], a, bb);
                    }
                }
            }
        }

        // LSTM pointwise epilogue — all 4 gates for (b,j) on this thread
        float hn4[4];
        #pragma unroll
        for (int k = 0; k < 4; k++) {
            float i_ = sigm(acc[0][k] + pv[0][k]);
            float f_ = sigm(acc[1][k] + pv[1][k]);
            float gg = tanhf(acc[2][k] + pv[2][k]);
            float o_ = sigm(acc[3][k] + pv[3][k]);
            float cn = f_ * creg[k] + i_ * gg;
            creg[k] = cn;
            float hn = o_ * tanhf(cn);
            hn4[k] = hn;
            int r = row_base + ((k >> 1) << 3);
            int u = ucol + (k & 1);
            if (!last)
                g_inter[(size_t)dir * 16777216 + ((size_t)t * 128 + r) * 512 + u] = hn;
            else
                out[((size_t)r * 256 + t) * 1024 + dir * 512 + u] = hn;
        }

        if (s < 255) {
            // repack this warp's 16x8 h tile into A-fragment order, publish
            int rl = lane >> 2, cl = 2 * (lane & 3);
            ht[rl * 9 + cl]           = f2tf(hn4[0]);
            ht[rl * 9 + cl + 1]       = f2tf(hn4[1]);
            ht[(rl + 8) * 9 + cl]     = f2tf(hn4[2]);
            ht[(rl + 8) * 9 + cl + 1] = f2tf(hn4[3]);
            __syncwarp();
            float4 fr;
            fr.x = ht[(lane >> 2) * 9 + (lane & 3)];
            fr.y = ht[((lane >> 2) + 8) * 9 + (lane & 3)];
            fr.z = ht[(lane >> 2) * 9 + (lane & 3) + 4];
            fr.w = ht[((lane >> 2) + 8) * 9 + (lane & 3) + 4];
            __syncwarp();
            g_hf[(((1 - p) * 2 + dir) << 14) + (myslice * 8 + warp) * 32 + lane] = fr;

            // per-direction grid barrier (cumulative counters, wrap-safe)
            __syncthreads();
            if (tid == 0) {
                __threadfence();
                unsigned old = atomicAdd(&g_arrive[dir], 1u);
                if ((old & 63u) == 63u) {
                    __threadfence();
                    atomicAdd(&g_gen[dir], 1u);
                } else {
                    unsigned target = gen_base + (unsigned)(s + 1);
                    while ((int)(atomicAdd(&g_gen[dir], 0u) - target) < 0)
                        __nanosleep(32);
                }
                __threadfence();
            }
            __syncthreads();
        }
        p ^= 1;
    }
}

// ---------------- launch ------------------------------------------------------
extern "C" void kernel_launch(void* const* d_in, const int* in_sizes, int n_in,
                              void* d_out, int out_size)
{
    (void)in_sizes; (void)n_in; (void)out_size;
    const float* x  = (const float*)d_in[0];
    const float* Wx = (const float*)d_in[1];
    const float* Wh = (const float*)d_in[2];
    const float* b  = (const float*)d_in[3];
    float* out = (float*)d_out;

    // idempotent, capture-legal; no static guards (harness rule)
    cudaFuncSetAttribute(scan_kernel,
                         cudaFuncAttributeMaxDynamicSharedMemorySize, SCAN_SMEM);

    dim3 gx(32, 256, 2);
    dim3 gs(64, 2);

    xproj_kernel<<<gx, 256>>>(x, Wx, b, 0, 0);
    scan_kernel<<<gs, 256, SCAN_SMEM>>>(Wh, 0, 0, out);
    xproj_kernel<<<gx, 256>>>(x, Wx, b, 1, 1);
    scan_kernel<<<gs, 256, SCAN_SMEM>>>(Wh, 1, 1, out);
}